// round 1
// baseline (speedup 1.0000x reference)
#include <cuda_runtime.h>
#include <math.h>

// Problem constants (b=2, c=64, H=480, W=640, gs=8 -> hc=60, wc=80, n=4800)
#define BQ 2
#define CC 64
#define HC 60
#define WCC 80
#define NN 4800
#define HH 480
#define WW 640
#define EPSF 1e-8f

// Main-kernel tiling
#define MCHUNKS 8
#define NCHUNK (NN / MCHUNKS)   // 600
#define MT 120
#define NTILES (NCHUNK / MT)    // 5
#define RB 256                  // rows (threads) per block
#define RBLOCKS ((NN + RB - 1) / RB)  // 19

typedef unsigned long long ull;

// ---------------- scratch (no allocations allowed) ----------------
__device__ float g_visPen[BQ * NN];          // (1 - cell_vis) * 5  in {0,5}
__device__ float g_posSim[BQ * NN];
__device__ float g_match[BQ * NN];
__device__ int   g_neigh[BQ * NN * 4];
__device__ float g_minPart[MCHUNKS][BQ * NN];

// ---------------- packed f32x2 helpers ----------------
__device__ __forceinline__ ull pack2(float x, float y) {
    ull r; asm("mov.b64 %0,{%1,%2};" : "=l"(r) : "f"(x), "f"(y)); return r;
}
__device__ __forceinline__ void unpack2(ull v, float &x, float &y) {
    asm("mov.b64 {%0,%1},%2;" : "=f"(x), "=f"(y) : "l"(v));
}
__device__ __forceinline__ void ffma2(ull &d, ull a, ull b) {
    asm("fma.rn.f32x2 %0,%1,%2,%0;" : "+l"(d) : "l"(a), "l"(b));
}

__device__ __forceinline__ float inb_pix(float yi, float xi) {
    return (yi >= 0.f && yi <= (float)(HH - 1) && xi >= 0.f && xi <= (float)(WW - 1)) ? 1.f : 0.f;
}
__device__ __forceinline__ float inb_grid(float yi, float xi) {
    return (yi >= 0.f && yi <= (float)(HC - 1) && xi >= 0.f && xi <= (float)(WCC - 1)) ? 1.f : 0.f;
}

// ============ Kernel 1: visibility per 8x8 cell (warp per cell) ============
__global__ void vis_kernel(const float* __restrict__ homo21) {
    int w = blockIdx.x * 8 + (threadIdx.x >> 5);
    if (w >= BQ * NN) return;
    int lane = threadIdx.x & 31;
    int b = w / NN, r = w % NN;
    int iy = r / WCC, ix = r % WCC;
    const float* h = homo21 + b * 9;
    float h0 = h[0], h1 = h[1], h2 = h[2], h3 = h[3], h4 = h[4],
          h5 = h[5], h6 = h[6], h7 = h[7], h8 = h[8];
    bool ok = true;
#pragma unroll
    for (int pp = 0; pp < 2; ++pp) {
        int p = lane + pp * 32;               // pixel 0..63 in the cell
        float x = (float)(ix * 8 + (p & 7));  // pix_xy centers with gs=1: (x, y) = (col, row)
        float y = (float)(iy * 8 + (p >> 3));
        float qx = h0 * x + h1 * y + h2;
        float qy = h3 * x + h4 * y + h5;
        float qz = h6 * x + h7 * y + h8;
        float wx = qx / (qz + EPSF);
        float wy = qy / (qz + EPSF);
        // bilinear(ones) at (wy, wx), image H x W, zero-fill outside
        float y0 = floorf(wy), x0 = floorf(wx);
        float fy = wy - y0, fx = wx - x0;
        float val = (1.f - fy) * (1.f - fx) * inb_pix(y0, x0)
                  + (1.f - fy) * fx         * inb_pix(y0, x0 + 1.f)
                  + fy * (1.f - fx)         * inb_pix(y0 + 1.f, x0)
                  + fy * fx                 * inb_pix(y0 + 1.f, x0 + 1.f);
        ok = ok && (val > 0.f);
    }
    unsigned all = __all_sync(0xffffffffu, ok);
    if (lane == 0) g_visPen[b * NN + r] = all ? 0.f : 5.f;
}

// ===== Kernel 2: per-row warp, bilinear w_desc1, pos_sim, match, 4-NN =====
__global__ void row_kernel(const float* __restrict__ desc1,
                           const float* __restrict__ desc2,
                           const float* __restrict__ homo12) {
    int w = blockIdx.x * 8 + (threadIdx.x >> 5);
    if (w >= BQ * NN) return;
    int lane = threadIdx.x & 31;
    int b = w / NN, r = w % NN;
    int iy = r / WCC, ix = r % WCC;
    const float* h = homo12 + b * 9;
    float px = (float)(ix * 8) + 3.5f;
    float py = (float)(iy * 8) + 3.5f;
    float qx = h[0] * px + h[1] * py + h[2];
    float qy = h[3] * px + h[4] * py + h[5];
    float qz = h[6] * px + h[7] * py + h[8];
    float wx = qx / (qz + EPSF);
    float wy = qy / (qz + EPSF);

    // sample desc2 at grid coords d_yx = (w_yx - 3.5) / 8
    float dyc = (wy - 3.5f) * 0.125f;
    float dxc = (wx - 3.5f) * 0.125f;
    float y0 = floorf(dyc), x0 = floorf(dxc);
    float fy = dyc - y0, fx = dxc - x0;
    float e00 = (1.f - fy) * (1.f - fx) * inb_grid(y0, x0);
    float e01 = (1.f - fy) * fx         * inb_grid(y0, x0 + 1.f);
    float e10 = fy * (1.f - fx)         * inb_grid(y0 + 1.f, x0);
    float e11 = fy * fx                 * inb_grid(y0 + 1.f, x0 + 1.f);
    int yc0 = (int)fminf(fmaxf(y0, 0.f), (float)(HC - 1));
    int yc1 = (int)fminf(fmaxf(y0 + 1.f, 0.f), (float)(HC - 1));
    int xc0 = (int)fminf(fmaxf(x0, 0.f), (float)(WCC - 1));
    int xc1 = (int)fminf(fmaxf(x0 + 1.f, 0.f), (float)(WCC - 1));

    float sq = 0.f, dp = 0.f;
#pragma unroll
    for (int pp = 0; pp < 2; ++pp) {
        int ch = lane + 32 * pp;
        const float* base = desc2 + (size_t)(b * CC + ch) * NN;
        float v = e00 * base[yc0 * WCC + xc0] + e01 * base[yc0 * WCC + xc1]
                + e10 * base[yc1 * WCC + xc0] + e11 * base[yc1 * WCC + xc1];
        sq += v * v;
        dp += desc1[(size_t)(b * CC + ch) * NN + r] * v;
    }
#pragma unroll
    for (int off = 16; off; off >>= 1) {
        sq += __shfl_xor_sync(0xffffffffu, sq, off);
        dp += __shfl_xor_sync(0xffffffffu, dp, off);
    }

    if (lane == 0) {
        float norm = sqrtf(sq);
        float posdot = dp / (norm + EPSF);
        g_posSim[b * NN + r] = sqrtf(fmaxf(2.f - 2.f * posdot, EPSF));
        g_match[b * NN + r] =
            (wy >= 0.f && wy <= (float)(HH - 1) && wx >= 0.f && wx <= (float)(WW - 1)) ? 1.f : 0.f;

        // 4 nearest grid centers (yx), matching top_k(-dist,4) with tie -> lower index.
        // The 4 nearest always lie inside the clamped 4x4 window around floor index.
        float a2 = wy * wy + wx * wx;
        int xlo = (int)fminf(fmaxf(floorf(dxc) - 1.f, 0.f), (float)(WCC - 4));
        int ylo = (int)fminf(fmaxf(floorf(dyc) - 1.f, 0.f), (float)(HC - 4));
        float bd[4] = {1e30f, 1e30f, 1e30f, 1e30f};
        int bi[4] = {-1, -1, -1, -1};
#pragma unroll
        for (int jy = 0; jy < 4; ++jy) {
            int iyc = ylo + jy;
            float cy = (float)(iyc * 8) + 3.5f;
#pragma unroll
            for (int jx = 0; jx < 4; ++jx) {
                int ixc = xlo + jx;
                float cx = (float)(ixc * 8) + 3.5f;
                float b2 = cy * cy + cx * cx;
                float cr = wy * cy + wx * cx;
                float d = sqrtf(fmaxf(a2 + b2 - 2.f * cr, 0.f));
                int m = iyc * WCC + ixc;
                if (d < bd[3]) {   // strict <: earlier (lower) index wins ties
                    int k = 3;
                    while (k > 0 && d < bd[k - 1]) {
                        bd[k] = bd[k - 1]; bi[k] = bi[k - 1]; --k;
                    }
                    bd[k] = d; bi[k] = m;
                }
            }
        }
        int* out = &g_neigh[(size_t)(b * NN + r) * 4];
        out[0] = bi[0]; out[1] = bi[1]; out[2] = bi[2]; out[3] = bi[3];
    }
}

// ===== Kernel 3: n x n desc_sim row-min (fp32x2 packed FMA, smem-tiled) =====
__global__ void __launch_bounds__(RB)
main_kernel(const float* __restrict__ desc1, const float* __restrict__ desc2) {
    __shared__ float sbf[CC * MT];   // [cp][mm] as f32x2 pairs (flat)
    __shared__ float vs[MT];

    int tid = threadIdx.x;
    int chunk = blockIdx.x;
    int row = blockIdx.y * RB + tid;
    int b = blockIdx.z;
    bool active = row < NN;

    ull a[32];
    int nb0 = -1, nb1 = -1, nb2 = -1, nb3 = -1;
    if (active) {
#pragma unroll
        for (int cp = 0; cp < 32; ++cp) {
            float x = desc1[(size_t)(b * CC + 2 * cp) * NN + row];
            float y = desc1[(size_t)(b * CC + 2 * cp + 1) * NN + row];
            a[cp] = pack2(x, y);
        }
        const int* nb = &g_neigh[(size_t)(b * NN + row) * 4];
        nb0 = nb[0]; nb1 = nb[1]; nb2 = nb[2]; nb3 = nb[3];
    }

    float tmin = 1e30f;   // min of (2 - 2 dot) over unpenalized columns
    float smin = 1e30f;   // min of sqrt(...) + penalties over penalized columns
    int mbase = chunk * NCHUNK;

    for (int tile = 0; tile < NTILES; ++tile) {
        int mt0 = mbase + tile * MT;
        // stage d2 tile: sbf packs channels (2cp, 2cp+1) as f32x2 at [cp*MT + mm]
        for (int i = tid; i < CC * MT; i += RB) {
            int ch = i / MT;
            int mm = i - ch * MT;
            sbf[(ch >> 1) * (MT * 2) + mm * 2 + (ch & 1)] =
                desc2[(size_t)(b * CC + ch) * NN + mt0 + mm];
        }
        for (int i = tid; i < MT; i += RB) vs[i] = g_visPen[b * NN + mt0 + i];
        __syncthreads();

        if (active) {
            const ulonglong2* bp2 = reinterpret_cast<const ulonglong2*>(sbf);
#pragma unroll 1
            for (int g = 0; g < MT / 4; ++g) {
                int mm0 = g * 4;
                ull acc0 = 0ull, acc1 = 0ull, acc2 = 0ull, acc3 = 0ull;
#pragma unroll
                for (int cp = 0; cp < 32; ++cp) {
                    int base = (cp * MT + mm0) >> 1;   // 16B-aligned
                    ulonglong2 q0 = bp2[base];
                    ulonglong2 q1 = bp2[base + 1];
                    ffma2(acc0, a[cp], q0.x);
                    ffma2(acc1, a[cp], q0.y);
                    ffma2(acc2, a[cp], q1.x);
                    ffma2(acc3, a[cp], q1.y);
                }
#pragma unroll
                for (int k = 0; k < 4; ++k) {
                    ull acc = (k == 0) ? acc0 : (k == 1) ? acc1 : (k == 2) ? acc2 : acc3;
                    float x, y; unpack2(acc, x, y);
                    float dot = x + y;
                    float t = 2.0f - 2.0f * dot;
                    int gm = mt0 + mm0 + k;
                    bool isn = (gm == nb0) | (gm == nb1) | (gm == nb2) | (gm == nb3);
                    float vp = vs[mm0 + k];
                    if (!isn && vp == 0.0f) {
                        tmin = fminf(tmin, t);
                    } else {
                        float s = sqrtf(fmaxf(t, EPSF)) + vp + (isn ? 5.0f : 0.0f);
                        smin = fminf(smin, s);
                    }
                }
            }
        }
        __syncthreads();
    }

    if (active) {
        float cand = sqrtf(fmaxf(tmin, EPSF));  // sqrt monotone: min commutes
        g_minPart[chunk][b * NN + row] = fminf(cand, smin);
    }
}

// ============ Kernel 4: deterministic final reduction -> scalar ============
__global__ void final_kernel(float* __restrict__ out) {
    __shared__ float sL[512], sM[512];
    int tid = threadIdx.x;
    float aL = 0.f, aM = 0.f;
    for (int i = tid; i < BQ * NN; i += 512) {
        float neg = g_minPart[0][i];
#pragma unroll
        for (int c = 1; c < MCHUNKS; ++c) neg = fminf(neg, g_minPart[c][i]);
        float l = g_posSim[i] - neg + 1.0f;
        l = fmaxf(l, 0.f);
        l = l * l;
        float m = g_match[i];
        aL += l * m;
        aM += m;
    }
    sL[tid] = aL; sM[tid] = aM;
    __syncthreads();
    for (int s = 256; s; s >>= 1) {
        if (tid < s) { sL[tid] += sL[tid + s]; sM[tid] += sM[tid + s]; }
        __syncthreads();
    }
    if (tid == 0) out[0] = sL[0] / sM[0];
}

// ---------------- launch ----------------
extern "C" void kernel_launch(void* const* d_in, const int* in_sizes, int n_in,
                              void* d_out, int out_size) {
    // metadata order: score1, score2, desc1, desc2, homo12, homo21
    const float* desc1  = (const float*)d_in[2];
    const float* desc2  = (const float*)d_in[3];
    const float* homo12 = (const float*)d_in[4];
    const float* homo21 = (const float*)d_in[5];

    vis_kernel<<<(BQ * NN + 7) / 8, 256>>>(homo21);
    row_kernel<<<(BQ * NN + 7) / 8, 256>>>(desc1, desc2, homo12);
    dim3 g3(MCHUNKS, RBLOCKS, BQ);
    main_kernel<<<g3, RB>>>(desc1, desc2);
    final_kernel<<<1, 512>>>((float*)d_out);
}

// round 2
// speedup vs baseline: 1.2672x; 1.2672x over previous
#include <cuda_runtime.h>
#include <math.h>

// Problem constants (b=2, c=64, H=480, W=640, gs=8 -> hc=60, wc=80, n=4800)
#define BQ 2
#define CC 64
#define HC 60
#define WCC 80
#define NN 4800
#define HH 480
#define WW 640
#define EPSF 1e-8f

// Mega-kernel tiling: 128-thread blocks, 16 column chunks of 300, tiles of 100
#define TB 128
#define CH 16
#define KC (NN / CH)          // 300
#define MT 100
#define NTILES (KC / MT)      // 3
#define RBLK ((NN + TB - 1) / TB)   // 38
#define TOTALB (CH * RBLK * BQ)     // 1216

typedef unsigned long long ull;

// ---------------- scratch (no allocations allowed) ----------------
__device__ float    g_visPen[BQ * NN];   // (1 - cell_vis) * 5  in {0,5}
__device__ float    g_posSim[BQ * NN];
__device__ float    g_match[BQ * NN];
__device__ int      g_negMinI[BQ * NN]; // per-row min as int-cast positive float
__device__ unsigned g_ctr;

// ---------------- packed f32x2 helpers ----------------
__device__ __forceinline__ ull pack2(float x, float y) {
    ull r; asm("mov.b64 %0,{%1,%2};" : "=l"(r) : "f"(x), "f"(y)); return r;
}
__device__ __forceinline__ void unpack2(ull v, float &x, float &y) {
    asm("mov.b64 {%0,%1},%2;" : "=f"(x), "=f"(y) : "l"(v));
}
__device__ __forceinline__ void ffma2(ull &d, ull a, ull b) {
    asm("fma.rn.f32x2 %0,%1,%2,%0;" : "+l"(d) : "l"(a), "l"(b));
}

__device__ __forceinline__ float inb_pix(float yi, float xi) {
    return (yi >= 0.f && yi <= (float)(HH - 1) && xi >= 0.f && xi <= (float)(WW - 1)) ? 1.f : 0.f;
}
__device__ __forceinline__ float inb_grid(float yi, float xi) {
    return (yi >= 0.f && yi <= (float)(HC - 1) && xi >= 0.f && xi <= (float)(WCC - 1)) ? 1.f : 0.f;
}

// ====== Kernel 0: visibility per 8x8 cell (warp/cell) + per-call init ======
__global__ void init_kernel(const float* __restrict__ homo21) {
    if (blockIdx.x == 0 && threadIdx.x == 0) g_ctr = 0u;
    int w = blockIdx.x * 8 + (threadIdx.x >> 5);
    if (w >= BQ * NN) return;
    int lane = threadIdx.x & 31;
    int b = w / NN, r = w % NN;
    int iy = r / WCC, ix = r % WCC;
    const float* h = homo21 + b * 9;
    float h0 = h[0], h1 = h[1], h2 = h[2], h3 = h[3], h4 = h[4],
          h5 = h[5], h6 = h[6], h7 = h[7], h8 = h[8];
    bool ok = true;
#pragma unroll
    for (int pp = 0; pp < 2; ++pp) {
        int p = lane + pp * 32;               // pixel 0..63 in the cell
        float x = (float)(ix * 8 + (p & 7));
        float y = (float)(iy * 8 + (p >> 3));
        float qx = h0 * x + h1 * y + h2;
        float qy = h3 * x + h4 * y + h5;
        float qz = h6 * x + h7 * y + h8;
        float wx = qx / (qz + EPSF);
        float wy = qy / (qz + EPSF);
        float y0 = floorf(wy), x0 = floorf(wx);
        float fy = wy - y0, fx = wx - x0;
        float val = (1.f - fy) * (1.f - fx) * inb_pix(y0, x0)
                  + (1.f - fy) * fx         * inb_pix(y0, x0 + 1.f)
                  + fy * (1.f - fx)         * inb_pix(y0 + 1.f, x0)
                  + fy * fx                 * inb_pix(y0 + 1.f, x0 + 1.f);
        ok = ok && (val > 0.f);
    }
    unsigned all = __all_sync(0xffffffffu, ok);
    if (lane == 0) {
        g_visPen[b * NN + r] = all ? 0.f : 5.f;
        g_negMinI[b * NN + r] = 0x7F800000;   // +inf
    }
}

// ====== Kernel 1: everything else, fused ======
__global__ void __launch_bounds__(TB, 3)
mega_kernel(const float* __restrict__ desc1, const float* __restrict__ desc2,
            const float* __restrict__ homo12, float* __restrict__ out) {
    __shared__ __align__(16) float sbf[CC * MT];   // d2 tile, channel pairs interleaved
    __shared__ __align__(16) float vs[MT];
    __shared__ int s_last;
    __shared__ float rL[TB / 32], rM[TB / 32];

    int tid = threadIdx.x;
    int chunk = blockIdx.x;
    int row = blockIdx.y * TB + tid;
    int b = blockIdx.z;
    bool active = row < NN;

    ull a[32];
    int nb0 = -1, nb1 = -1, nb2 = -1, nb3 = -1;

    if (active) {
        // row descriptor (coalesced over row)
#pragma unroll
        for (int cp = 0; cp < 32; ++cp) {
            float x = desc1[(size_t)(b * CC + 2 * cp) * NN + row];
            float y = desc1[(size_t)(b * CC + 2 * cp + 1) * NN + row];
            a[cp] = pack2(x, y);
        }
        // warp point
        int iy = row / WCC, ix = row % WCC;
        const float* h = homo12 + b * 9;
        float px = (float)(ix * 8) + 3.5f;
        float py = (float)(iy * 8) + 3.5f;
        float qx = h[0] * px + h[1] * py + h[2];
        float qy = h[3] * px + h[4] * py + h[5];
        float qz = h[6] * px + h[7] * py + h[8];
        float wx = qx / (qz + EPSF);
        float wy = qy / (qz + EPSF);
        float dyc = (wy - 3.5f) * 0.125f;
        float dxc = (wx - 3.5f) * 0.125f;

        // 4 nearest grid centers (tie -> lower index), inside clamped 4x4 window
        {
            float a2 = wy * wy + wx * wx;
            int xlo = (int)fminf(fmaxf(floorf(dxc) - 1.f, 0.f), (float)(WCC - 4));
            int ylo = (int)fminf(fmaxf(floorf(dyc) - 1.f, 0.f), (float)(HC - 4));
            float bd[4] = {1e30f, 1e30f, 1e30f, 1e30f};
            int bi[4] = {-1, -1, -1, -1};
#pragma unroll
            for (int jy = 0; jy < 4; ++jy) {
                int iyc = ylo + jy;
                float cy = (float)(iyc * 8) + 3.5f;
#pragma unroll
                for (int jx = 0; jx < 4; ++jx) {
                    int ixc = xlo + jx;
                    float cx = (float)(ixc * 8) + 3.5f;
                    float d = sqrtf(fmaxf(a2 + cy * cy + cx * cx - 2.f * (wy * cy + wx * cx), 0.f));
                    int m = iyc * WCC + ixc;
                    if (d < bd[3]) {
                        int k = 3;
                        while (k > 0 && d < bd[k - 1]) {
                            bd[k] = bd[k - 1]; bi[k] = bi[k - 1]; --k;
                        }
                        bd[k] = d; bi[k] = m;
                    }
                }
            }
            nb0 = bi[0]; nb1 = bi[1]; nb2 = bi[2]; nb3 = bi[3];
        }

        // pos_sim + match: only chunk-0 blocks write (avoid 16x redundancy)
        if (chunk == 0) {
            float y0 = floorf(dyc), x0 = floorf(dxc);
            float fy = dyc - y0, fx = dxc - x0;
            float e00 = (1.f - fy) * (1.f - fx) * inb_grid(y0, x0);
            float e01 = (1.f - fy) * fx         * inb_grid(y0, x0 + 1.f);
            float e10 = fy * (1.f - fx)         * inb_grid(y0 + 1.f, x0);
            float e11 = fy * fx                 * inb_grid(y0 + 1.f, x0 + 1.f);
            int yc0 = (int)fminf(fmaxf(y0, 0.f), (float)(HC - 1));
            int yc1 = (int)fminf(fmaxf(y0 + 1.f, 0.f), (float)(HC - 1));
            int xc0 = (int)fminf(fmaxf(x0, 0.f), (float)(WCC - 1));
            int xc1 = (int)fminf(fmaxf(x0 + 1.f, 0.f), (float)(WCC - 1));
            float sq = 0.f, dp = 0.f;
#pragma unroll
            for (int cp = 0; cp < 32; ++cp) {
                float d1x, d1y; unpack2(a[cp], d1x, d1y);
                const float* b0 = desc2 + (size_t)(b * CC + 2 * cp) * NN;
                const float* b1 = b0 + NN;
                float v0 = e00 * b0[yc0 * WCC + xc0] + e01 * b0[yc0 * WCC + xc1]
                         + e10 * b0[yc1 * WCC + xc0] + e11 * b0[yc1 * WCC + xc1];
                float v1 = e00 * b1[yc0 * WCC + xc0] + e01 * b1[yc0 * WCC + xc1]
                         + e10 * b1[yc1 * WCC + xc0] + e11 * b1[yc1 * WCC + xc1];
                sq += v0 * v0 + v1 * v1;
                dp += d1x * v0 + d1y * v1;
            }
            float posdot = dp / (sqrtf(sq) + EPSF);
            g_posSim[b * NN + row] = sqrtf(fmaxf(2.f - 2.f * posdot, EPSF));
            g_match[b * NN + row] =
                (wy >= 0.f && wy <= (float)(HH - 1) && wx >= 0.f && wx <= (float)(WW - 1)) ? 1.f : 0.f;
        }
    }

    // ---- main loop: 300 columns of desc_sim, dual-track min ----
    float tmin = 1e30f;   // min of (2 - 2 dot) over unpenalized columns
    float smin = 1e30f;   // min of sqrt(...) + penalties over penalized columns
    int mbase = chunk * KC;

    for (int tile = 0; tile < NTILES; ++tile) {
        int mt0 = mbase + tile * MT;
        for (int i = tid; i < CC * MT; i += TB) {
            int ch = i / MT;
            int mm = i - ch * MT;
            sbf[(ch >> 1) * (MT * 2) + mm * 2 + (ch & 1)] =
                desc2[(size_t)(b * CC + ch) * NN + mt0 + mm];
        }
        for (int i = tid; i < MT; i += TB) vs[i] = g_visPen[b * NN + mt0 + i];
        __syncthreads();

        if (active) {
            const ulonglong2* bp2 = reinterpret_cast<const ulonglong2*>(sbf);
#pragma unroll 1
            for (int g = 0; g < MT / 4; ++g) {
                int mm0 = g * 4;
                ull acc0 = 0ull, acc1 = 0ull, acc2 = 0ull, acc3 = 0ull;
#pragma unroll
                for (int cp = 0; cp < 32; ++cp) {
                    int base = (cp * MT + mm0) >> 1;   // 16B-aligned
                    ulonglong2 q0 = bp2[base];
                    ulonglong2 q1 = bp2[base + 1];
                    ffma2(acc0, a[cp], q0.x);
                    ffma2(acc1, a[cp], q0.y);
                    ffma2(acc2, a[cp], q1.x);
                    ffma2(acc3, a[cp], q1.y);
                }
                float4 vp4 = *reinterpret_cast<const float4*>(&vs[mm0]);
#pragma unroll
                for (int k = 0; k < 4; ++k) {
                    ull acc = (k == 0) ? acc0 : (k == 1) ? acc1 : (k == 2) ? acc2 : acc3;
                    float x, y; unpack2(acc, x, y);
                    float t = 2.0f - 2.0f * (x + y);
                    int gm = mt0 + mm0 + k;
                    bool isn = (gm == nb0) | (gm == nb1) | (gm == nb2) | (gm == nb3);
                    float vp = (k == 0) ? vp4.x : (k == 1) ? vp4.y : (k == 2) ? vp4.z : vp4.w;
                    if (!isn && vp == 0.0f) {
                        tmin = fminf(tmin, t);
                    } else {
                        float s = sqrtf(fmaxf(t, EPSF)) + vp + (isn ? 5.0f : 0.0f);
                        smin = fminf(smin, s);
                    }
                }
            }
        }
        __syncthreads();
    }

    if (active) {
        float val = fminf(sqrtf(fmaxf(tmin, EPSF)), smin);
        atomicMin(&g_negMinI[b * NN + row], __float_as_int(val));
    }

    // ---- last block finishes: deterministic final reduction ----
    __syncthreads();
    if (tid == 0) {
        __threadfence();
        unsigned r = atomicAdd(&g_ctr, 1u);
        s_last = (r == TOTALB - 1) ? 1 : 0;
    }
    __syncthreads();
    if (s_last) {
        __threadfence();
        float aL = 0.f, aM = 0.f;
        for (int i = tid; i < BQ * NN; i += TB) {
            float neg = __int_as_float(g_negMinI[i]);
            float l = fmaxf(g_posSim[i] - neg + 1.0f, 0.f);
            float m = g_match[i];
            aL += l * l * m;
            aM += m;
        }
#pragma unroll
        for (int off = 16; off; off >>= 1) {
            aL += __shfl_xor_sync(0xffffffffu, aL, off);
            aM += __shfl_xor_sync(0xffffffffu, aM, off);
        }
        if ((tid & 31) == 0) { rL[tid >> 5] = aL; rM[tid >> 5] = aM; }
        __syncthreads();
        if (tid == 0) {
            float sL = 0.f, sM = 0.f;
#pragma unroll
            for (int wnum = 0; wnum < TB / 32; ++wnum) { sL += rL[wnum]; sM += rM[wnum]; }
            out[0] = sL / sM;
        }
    }
}

// ---------------- launch ----------------
extern "C" void kernel_launch(void* const* d_in, const int* in_sizes, int n_in,
                              void* d_out, int out_size) {
    // metadata order: score1, score2, desc1, desc2, homo12, homo21
    const float* desc1  = (const float*)d_in[2];
    const float* desc2  = (const float*)d_in[3];
    const float* homo12 = (const float*)d_in[4];
    const float* homo21 = (const float*)d_in[5];

    init_kernel<<<(BQ * NN + 7) / 8, 256>>>(homo21);
    dim3 g(CH, RBLK, BQ);
    mega_kernel<<<g, TB>>>(desc1, desc2, homo12, (float*)d_out);
}